// round 12
// baseline (speedup 1.0000x reference)
#include <cuda_runtime.h>

// Problem dims (fixed by the reference)
#define Bn 8
#define Cn 8
#define Hn 512
#define Wn 512
#define HWn (Hn * Wn)

#define TILE_W 32
#define TILE_H 16
#define HALO_W (TILE_W + 2)   // 34
#define HALO_H (TILE_H + 2)   // 18
#define NT     (TILE_W * TILE_H)   // 512 threads
#define ELEMS  (HALO_W * HALO_H)   // 612
#define GRID_X (Wn / TILE_W)       // 16
#define GRID_Y (Hn / TILE_H)       // 32
#define NBLOCKS (GRID_X * GRID_Y * Bn)  // 4096

// Per-block partial sums: x = NC-normalized part, y = NP-normalized part.
__device__ float2 g_part[NBLOCKS];
__device__ unsigned int g_ticket = 0;   // last-block detector; reset to 0 each run

__device__ __forceinline__ float ex2f(float x) {
    float r; asm("ex2.approx.f32 %0, %1;" : "=f"(r) : "f"(x)); return r;
}
__device__ __forceinline__ float lg2f(float x) {
    float r; asm("lg2.approx.f32 %0, %1;" : "=f"(r) : "f"(x)); return r;
}

__global__ __launch_bounds__(NT, 2) void bicon_kernel(
    const float* __restrict__ atts,
    const float* __restrict__ dets,
    const float* __restrict__ target,
    const float* __restrict__ con,
    float* __restrict__ out)
{
    const float L2E = 1.4426950408889634f;
    const float LN2 = 0.6931471805599453f;

    // 8-neighborhood in raster order; vote channel k pairs center channel k
    // with channel (7-k) at offset (DH[k], DW[k]).  (Validated rel_err 0.0.)
    const int DH[8] = {-1, -1, -1,  0, 0,  1, 1, 1};
    const int DW[8] = {-1,  0,  1, -1, 1, -1, 0, 1};

    __shared__ float sm[16][HALO_H][HALO_W];          // log-sigmoid tiles
    __shared__ unsigned int conb[TILE_H][TILE_W];     // packed con bits per pixel
    __shared__ float r0[16], r1[16];
    __shared__ int  s_last;

    const int tid = threadIdx.x;         // 0..511
    const int tx  = tid & 31;
    const int ty  = tid >> 5;
    const int w0  = blockIdx.x * TILE_W;
    const int h0  = blockIdx.y * TILE_H;
    const int b   = blockIdx.z;

    // ---------------- Phase 1: halo log-sigmoid tiles + conn BCE + con bitmask
    // Element slots: e0 = tid (always), e1 = tid + 512 (threads 0..99 only).
    const int e0   = tid;
    const int row0 = e0 / HALO_W;
    const int col0 = e0 - row0 * HALO_W;
    const int gh0  = h0 + row0 - 1;
    const int gw0  = w0 + col0 - 1;
    const bool valid0 = ((unsigned)gh0 < (unsigned)Hn) && ((unsigned)gw0 < (unsigned)Wn);
    const bool intr0  = (row0 >= 1) && (row0 <= TILE_H) && (col0 >= 1) && (col0 <= TILE_W);
    const int off0 = gh0 * Wn + gw0;

    const int e1   = tid + NT;
    const bool has1 = (e1 < ELEMS);
    const int row1 = e1 / HALO_W;
    const int col1 = e1 - row1 * HALO_W;
    const int gh1  = h0 + row1 - 1;
    const int gw1  = w0 + col1 - 1;
    const bool valid1 = has1 && ((unsigned)gh1 < (unsigned)Hn) && ((unsigned)gw1 < (unsigned)Wn);
    const bool intr1  = has1 && (row1 >= 1) && (row1 <= TILE_H) && (col1 >= 1) && (col1 <= TILE_W);
    const int off1 = gh1 * Wn + gw1;

    float connAcc = 0.0f;
    unsigned int bits0 = 0u, bits1 = 0u;

#pragma unroll
    for (int c = 0; c < Cn; c++) {
        const int base = (b * Cn + c) * HWn;

        // slot 0
        {
            float lp1 = -1e30f, lp2 = -1e30f;
            if (valid0) {
                const float x1 = __ldg(atts + base + off0);
                const float x2 = __ldg(dets + base + off0);
                const float s1 = LN2 * lg2f(1.0f + ex2f(x1 * L2E));  // softplus
                const float s2 = LN2 * lg2f(1.0f + ex2f(x2 * L2E));
                lp1 = x1 - s1;
                lp2 = x2 - s2;
                if (intr0) {
                    const float t = __ldg(con + base + off0);
                    connAcc += (s1 + s2) - t * (x1 + x2);
                    if (t > 0.5f) bits0 |= (1u << c);
                }
            }
            sm[c][row0][col0]     = lp1;
            sm[c + 8][row0][col0] = lp2;
        }
        // slot 1
        if (has1) {
            float lp1 = -1e30f, lp2 = -1e30f;
            if (valid1) {
                const float x1 = __ldg(atts + base + off1);
                const float x2 = __ldg(dets + base + off1);
                const float s1 = LN2 * lg2f(1.0f + ex2f(x1 * L2E));
                const float s2 = LN2 * lg2f(1.0f + ex2f(x2 * L2E));
                lp1 = x1 - s1;
                lp2 = x2 - s2;
                if (intr1) {
                    const float t = __ldg(con + base + off1);
                    connAcc += (s1 + s2) - t * (x1 + x2);
                    if (t > 0.5f) bits1 |= (1u << c);
                }
            }
            sm[c][row1][col1]     = lp1;
            sm[c + 8][row1][col1] = lp2;
        }
    }
    if (intr0) conb[row0 - 1][col0 - 1] = bits0;
    if (intr1) conb[row1 - 1][col1 - 1] = bits1;
    __syncthreads();

    // ---------------- Phase 2: per-pixel combine (one thread = one pixel)
    const unsigned int cb = conb[ty][tx];
    const int cnt = __popc(cb);
    const bool edge = (cnt > 0) && (cnt < 8);

    float bic1 = 0.0f, bic2 = 0.0f;
    float sv1 = 0.0f, sv2 = 0.0f;
    float mv2 = 1e30f;

#pragma unroll
    for (int k = 0; k < 8; k++) {
        const int rr = ty + 1 + DH[k];
        const int cc = tx + 1 + DW[k];

        const float lv1 = sm[k][ty + 1][tx + 1]     + sm[7 - k][rr][cc];
        const float lv2 = sm[8 + k][ty + 1][tx + 1] + sm[15 - k][rr][cc];

        const float v1 = ex2f(lv1 * L2E);
        const float v2 = ex2f(lv2 * L2E);
        sv1 += v1;
        sv2 += v2;
        mv2 = fminf(mv2, v2);

        const bool tp = (cb >> k) & 1u;
        const float l1 = tp ? fmaxf(lv1, -100.0f)
                            : fmaxf(LN2 * lg2f(1.0f - v1), -100.0f);
        const float l2 = tp ? fmaxf(lv2, -100.0f)
                            : fmaxf(LN2 * lg2f(1.0f - v2), -100.0f);
        bic1 -= l1;
        bic2 -= l2;
    }

    const int gh = h0 + ty;
    const int gw = w0 + tx;
    const float tgt  = __ldg(target + b * HWn + gh * Wn + gw);
    const bool  tpos = (tgt > 0.5f);

    const float g1   = sv1 * 0.125f;
    const float bce1 = tpos ? -fmaxf(LN2 * lg2f(g1),        -100.0f)
                            : -fmaxf(LN2 * lg2f(1.0f - g1), -100.0f);

    const float g2  = sv2 * 0.125f;
    const float dec = edge ? (1.0f - mv2) : g2;
    const float de2 = tpos ? -fmaxf(LN2 * lg2f(dec),        -100.0f)
                           : -fmaxf(LN2 * lg2f(1.0f - dec), -100.0f);

    float cNC = 0.2f * (bic1 + bic2) + 0.8f * connAcc;   // / (B*C*H*W)
    float cNP = bce1 + de2;                              // / (B*H*W)

    // ---------------- Block reduction -> g_part[bid]
#pragma unroll
    for (int off = 16; off > 0; off >>= 1) {
        cNC += __shfl_xor_sync(0xFFFFFFFFu, cNC, off);
        cNP += __shfl_xor_sync(0xFFFFFFFFu, cNP, off);
    }
    const int lane = tid & 31;
    const int wid  = tid >> 5;
    if (lane == 0) { r0[wid] = cNC; r1[wid] = cNP; }
    __syncthreads();

    const int bid = blockIdx.x + GRID_X * (blockIdx.y + GRID_Y * blockIdx.z);
    if (tid == 0) {
        float a = 0.0f, c2 = 0.0f;
#pragma unroll
        for (int i = 0; i < 16; i++) { a += r0[i]; c2 += r1[i]; }
        g_part[bid] = make_float2(a, c2);
        __threadfence();
        const unsigned int ticket = atomicAdd(&g_ticket, 1u);
        s_last = (ticket == NBLOCKS - 1) ? 1 : 0;
    }
    __syncthreads();

    // ---------------- Last block: final reduction + output
    if (s_last) {
        __threadfence();
        double a = 0.0, c2 = 0.0;
        for (int i = tid; i < NBLOCKS; i += NT) {
            const float2 p = g_part[i];
            a  += (double)p.x;
            c2 += (double)p.y;
        }
#pragma unroll
        for (int off = 16; off > 0; off >>= 1) {
            a  += __shfl_xor_sync(0xFFFFFFFFu, a,  off);
            c2 += __shfl_xor_sync(0xFFFFFFFFu, c2, off);
        }
        __shared__ double d0[16], d1[16];
        if (lane == 0) { d0[wid] = a; d1[wid] = c2; }
        __syncthreads();
        if (wid == 0) {
            double x = (lane < 16) ? d0[lane] : 0.0;
            double y = (lane < 16) ? d1[lane] : 0.0;
#pragma unroll
            for (int off = 8; off > 0; off >>= 1) {
                x += __shfl_xor_sync(0xFFFFFFFFu, x, off);
                y += __shfl_xor_sync(0xFFFFFFFFu, y, off);
            }
            if (lane == 0) {
                const double invNC = 1.0 / (double)(Bn * Cn * Hn * Wn);
                const double invNP = 1.0 / (double)(Bn * Hn * Wn);
                out[0] = (float)(x * invNC + y * invNP);
                g_ticket = 0;   // reset for next graph replay (deterministic)
            }
        }
    }
}

extern "C" void kernel_launch(void* const* d_in, const int* in_sizes, int n_in,
                              void* d_out, int out_size)
{
    const float* atts   = (const float*)d_in[0];
    const float* dets   = (const float*)d_in[1];
    const float* target = (const float*)d_in[2];
    const float* con    = (const float*)d_in[3];
    float* out = (float*)d_out;

    dim3 grid(GRID_X, GRID_Y, Bn);
    bicon_kernel<<<grid, NT>>>(atts, dets, target, con, out);
}

// round 13
// speedup vs baseline: 1.1788x; 1.1788x over previous
#include <cuda_runtime.h>

// Problem dims (fixed by the reference)
#define Bn 8
#define Cn 8
#define Hn 512
#define Wn 512
#define HWn (Hn * Wn)

#define TILE_W 32
#define TILE_H 16
#define HALO_W (TILE_W + 2)   // 34
#define HALO_H (TILE_H + 2)   // 18
#define NT     (TILE_W * TILE_H)   // 512 threads
#define ELEMS  (HALO_W * HALO_H)   // 612
#define GRID_X (Wn / TILE_W)       // 16
#define GRID_Y (Hn / TILE_H)       // 32
#define NBLOCKS (GRID_X * GRID_Y * Bn)  // 4096

// Per-block partial sums: x = NC-normalized part, y = NP-normalized part.
__device__ float2 g_part[NBLOCKS];
__device__ unsigned int g_ticket = 0;   // last-block detector; reset each run

__device__ __forceinline__ float ex2f(float x) {
    float r; asm("ex2.approx.f32 %0, %1;" : "=f"(r) : "f"(x)); return r;
}
__device__ __forceinline__ float lg2f(float x) {
    float r; asm("lg2.approx.f32 %0, %1;" : "=f"(r) : "f"(x)); return r;
}

// 4 CTAs/SM requires regs <= 32 (64K regfile / 2048 threads).
__global__ __launch_bounds__(NT, 4) void bicon_kernel(
    const float* __restrict__ atts,
    const float* __restrict__ dets,
    const float* __restrict__ target,
    const float* __restrict__ con,
    float* __restrict__ out)
{
    const float L2E = 1.4426950408889634f;
    const float LN2 = 0.6931471805599453f;

    // 8-neighborhood in raster order; vote channel k pairs center channel k
    // with channel (7-k) at offset (DH[k], DW[k]).  (Validated rel_err 0.0.)
    const int DH[8] = {-1, -1, -1,  0, 0,  1, 1, 1};
    const int DW[8] = {-1,  0,  1, -1, 1, -1, 0, 1};

    __shared__ float lp[Cn][HALO_H][HALO_W];          // one branch at a time (~19.6 KB)
    __shared__ unsigned char ct[Cn][TILE_H][TILE_W];  // binary con targets (4 KB)
    __shared__ float r0[16], r1[16];
    __shared__ int s_last;

    const int tid = threadIdx.x;         // 0..511
    const int tx  = tid & 31;
    const int ty  = tid >> 5;
    const int w0  = blockIdx.x * TILE_W;
    const int h0  = blockIdx.y * TILE_H;
    const int b   = blockIdx.z;

    float connAcc = 0.0f;

    // ---------------- Pass A load: atts log-sigmoid tiles + con bits + conn BCE(atts)
    for (int i = tid; i < Cn * ELEMS; i += NT) {
        const int c   = i / ELEMS;
        const int r   = i - c * ELEMS;
        const int row = r / HALO_W;
        const int col = r - row * HALO_W;
        const int gh  = h0 + row - 1;
        const int gw  = w0 + col - 1;
        const bool valid = ((unsigned)gh < (unsigned)Hn) && ((unsigned)gw < (unsigned)Wn);

        float lpv = -1e30f;
        if (valid) {
            const int gi = (b * Cn + c) * HWn + gh * Wn + gw;
            const float x = __ldg(atts + gi);
            const float s = LN2 * lg2f(1.0f + ex2f(x * L2E));  // softplus(x)
            lpv = x - s;                                       // log sigmoid(x)
            if (row >= 1 && row <= TILE_H && col >= 1 && col <= TILE_W) {
                const float t = __ldg(con + gi);
                connAcc += s - t * x;                          // BCE(sigmoid(x), t)
                ct[c][row - 1][col - 1] = (t > 0.5f) ? 1 : 0;
            }
        }
        lp[c][row][col] = lpv;
    }
    __syncthreads();

    // ---------------- Combine A (atts): bic1, sv1
    float bic1 = 0.0f, sv1 = 0.0f;
#pragma unroll
    for (int k = 0; k < 8; k++) {
        const float lv = lp[k][ty + 1][tx + 1]
                       + lp[7 - k][ty + 1 + DH[k]][tx + 1 + DW[k]];
        const float v = ex2f(lv * L2E);
        sv1 += v;
        bic1 -= ct[k][ty][tx] ? fmaxf(lv, -100.0f)
                              : fmaxf(LN2 * lg2f(1.0f - v), -100.0f);
    }
    __syncthreads();   // done reading lp before pass B overwrites it

    // ---------------- Pass B load: dets (t comes from ct bits, no con reload)
    for (int i = tid; i < Cn * ELEMS; i += NT) {
        const int c   = i / ELEMS;
        const int r   = i - c * ELEMS;
        const int row = r / HALO_W;
        const int col = r - row * HALO_W;
        const int gh  = h0 + row - 1;
        const int gw  = w0 + col - 1;
        const bool valid = ((unsigned)gh < (unsigned)Hn) && ((unsigned)gw < (unsigned)Wn);

        float lpv = -1e30f;
        if (valid) {
            const int gi = (b * Cn + c) * HWn + gh * Wn + gw;
            const float x = __ldg(dets + gi);
            const float s = LN2 * lg2f(1.0f + ex2f(x * L2E));
            lpv = x - s;
            if (row >= 1 && row <= TILE_H && col >= 1 && col <= TILE_W) {
                const float t = (float)ct[c][row - 1][col - 1];
                connAcc += s - t * x;
            }
        }
        lp[c][row][col] = lpv;
    }
    __syncthreads();

    // ---------------- Combine B (dets): bic2, sv2, min, edge
    float bic2 = 0.0f, sv2 = 0.0f, mv2 = 1e30f;
    int cnt = 0;
#pragma unroll
    for (int k = 0; k < 8; k++) {
        const float lv = lp[k][ty + 1][tx + 1]
                       + lp[7 - k][ty + 1 + DH[k]][tx + 1 + DW[k]];
        const float v = ex2f(lv * L2E);
        sv2 += v;
        mv2 = fminf(mv2, v);
        const int tp = ct[k][ty][tx];
        cnt += tp;
        bic2 -= tp ? fmaxf(lv, -100.0f)
                   : fmaxf(LN2 * lg2f(1.0f - v), -100.0f);
    }

    // ---------------- Per-pixel tails
    const float tgt  = __ldg(target + b * HWn + (h0 + ty) * Wn + (w0 + tx));
    const bool  tpos = (tgt > 0.5f);

    const float g1   = sv1 * 0.125f;
    const float bce1 = tpos ? -fmaxf(LN2 * lg2f(g1),        -100.0f)
                            : -fmaxf(LN2 * lg2f(1.0f - g1), -100.0f);

    const float g2   = sv2 * 0.125f;
    const bool  edge = (cnt > 0) && (cnt < 8);
    const float dec  = edge ? (1.0f - mv2) : g2;
    const float de2  = tpos ? -fmaxf(LN2 * lg2f(dec),        -100.0f)
                            : -fmaxf(LN2 * lg2f(1.0f - dec), -100.0f);

    float cNC = 0.2f * (bic1 + bic2) + 0.8f * connAcc;   // / (B*C*H*W)
    float cNP = bce1 + de2;                              // / (B*H*W)

    // ---------------- Block reduction -> g_part[bid]
#pragma unroll
    for (int off = 16; off > 0; off >>= 1) {
        cNC += __shfl_xor_sync(0xFFFFFFFFu, cNC, off);
        cNP += __shfl_xor_sync(0xFFFFFFFFu, cNP, off);
    }
    const int lane = tid & 31;
    const int wid  = tid >> 5;
    if (lane == 0) { r0[wid] = cNC; r1[wid] = cNP; }
    __syncthreads();

    if (tid == 0) {
        float a = 0.0f, c2 = 0.0f;
#pragma unroll
        for (int i = 0; i < 16; i++) { a += r0[i]; c2 += r1[i]; }
        const int bid = blockIdx.x + GRID_X * (blockIdx.y + GRID_Y * blockIdx.z);
        g_part[bid] = make_float2(a, c2);
        __threadfence();
        const unsigned int ticket = atomicAdd(&g_ticket, 1u);
        s_last = (ticket == NBLOCKS - 1) ? 1 : 0;
    }
    __syncthreads();

    // ---------------- Last block: final deterministic reduction + output
    if (s_last) {
        __threadfence();
        double a = 0.0, c2 = 0.0;
        for (int i = tid; i < NBLOCKS; i += NT) {
            const float2 p = g_part[i];
            a  += (double)p.x;
            c2 += (double)p.y;
        }
#pragma unroll
        for (int off = 16; off > 0; off >>= 1) {
            a  += __shfl_xor_sync(0xFFFFFFFFu, a,  off);
            c2 += __shfl_xor_sync(0xFFFFFFFFu, c2, off);
        }
        __shared__ double d0[16], d1[16];
        if (lane == 0) { d0[wid] = a; d1[wid] = c2; }
        __syncthreads();
        if (wid == 0) {
            double x = (lane < 16) ? d0[lane] : 0.0;
            double y = (lane < 16) ? d1[lane] : 0.0;
#pragma unroll
            for (int off = 8; off > 0; off >>= 1) {
                x += __shfl_xor_sync(0xFFFFFFFFu, x, off);
                y += __shfl_xor_sync(0xFFFFFFFFu, y, off);
            }
            if (lane == 0) {
                const double invNC = 1.0 / (double)(Bn * Cn * Hn * Wn);
                const double invNP = 1.0 / (double)(Bn * Hn * Wn);
                out[0] = (float)(x * invNC + y * invNP);
                g_ticket = 0;   // reset for next graph replay
            }
        }
    }
}

extern "C" void kernel_launch(void* const* d_in, const int* in_sizes, int n_in,
                              void* d_out, int out_size)
{
    const float* atts   = (const float*)d_in[0];
    const float* dets   = (const float*)d_in[1];
    const float* target = (const float*)d_in[2];
    const float* con    = (const float*)d_in[3];
    float* out = (float*)d_out;

    // Hint: leave enough smem carveout for 4 CTAs/SM (~96 KB). Harmless if ignored.
    cudaFuncSetAttribute(bicon_kernel,
                         cudaFuncAttributePreferredSharedMemoryCarveout, 50);

    dim3 grid(GRID_X, GRID_Y, Bn);
    bicon_kernel<<<grid, NT>>>(atts, dets, target, con, out);
}

// round 14
// speedup vs baseline: 1.6199x; 1.3742x over previous
#include <cuda_runtime.h>

// Problem dims (fixed by the reference)
#define Bn 8
#define Cn 8
#define Hn 512
#define Wn 512
#define HWn (Hn * Wn)

#define TILE_W 32
#define TILE_H 16
#define HALO_W (TILE_W + 2)   // 34
#define HALO_H (TILE_H + 2)   // 18
#define NT     (TILE_W * TILE_H)   // 512 threads
#define ELEMS  (HALO_W * HALO_H)   // 612
#define GRID_X (Wn / TILE_W)       // 16
#define GRID_Y (Hn / TILE_H)       // 32
#define NBLOCKS (GRID_X * GRID_Y * Bn)  // 4096

// Per-block partial sums: x = NC-normalized part, y = NP-normalized part.
__device__ float2 g_part[NBLOCKS];
__device__ unsigned int g_ticket = 0;   // last-block detector; reset each run

__device__ __forceinline__ float ex2f(float x) {
    float r; asm("ex2.approx.f32 %0, %1;" : "=f"(r) : "f"(x)); return r;
}
__device__ __forceinline__ float lg2f(float x) {
    float r; asm("lg2.approx.f32 %0, %1;" : "=f"(r) : "f"(x)); return r;
}

// 4 CTAs/SM requires regs <= 32 (64K regfile / 2048 threads).
__global__ __launch_bounds__(NT, 4) void bicon_kernel(
    const float* __restrict__ atts,
    const float* __restrict__ dets,
    const float* __restrict__ target,
    const float* __restrict__ con,
    float* __restrict__ out)
{
    const float L2E = 1.4426950408889634f;
    const float LN2 = 0.6931471805599453f;

    // 8-neighborhood in raster order; vote channel k pairs center channel k
    // with channel (7-k) at offset (DH[k], DW[k]).  (Validated rel_err 0.0.)
    const int DH[8] = {-1, -1, -1,  0, 0,  1, 1, 1};
    const int DW[8] = {-1,  0,  1, -1, 1, -1, 0, 1};

    __shared__ float lpf[Cn * ELEMS];                 // one branch of log-sigmoid (19.6 KB)
    __shared__ unsigned int conb[TILE_H][TILE_W];     // packed con bits per pixel (2 KB)
    __shared__ float r0[16], r1[16];
    __shared__ int s_last;

    const int tid = threadIdx.x;         // 0..511
    const int tx  = tid & 31;
    const int ty  = tid >> 5;
    const int w0  = blockIdx.x * TILE_W;
    const int h0  = blockIdx.y * TILE_H;
    const int b   = blockIdx.z;
    const long baseB = (long)b * Cn * HWn;

    // ---- Slot geometry, computed ONCE (kills per-iteration div/bounds ALU) ----
    // slot0 = tid (all threads); slot1 = tid + 512 (threads 0..99 only)
    const int row0 = tid / HALO_W;
    const int col0 = tid - row0 * HALO_W;
    const int gh0  = h0 + row0 - 1;
    const int gw0  = w0 + col0 - 1;
    const bool valid0 = ((unsigned)gh0 < (unsigned)Hn) && ((unsigned)gw0 < (unsigned)Wn);
    const bool intr0  = (row0 >= 1) && (col0 >= 1) && (col0 <= TILE_W);  // row0<=16 auto (tid<512 -> row0<=15+)
    const long off0 = (long)gh0 * Wn + gw0;
    const int sidx0 = tid;               // row0*HALO_W + col0 == tid

    const int e1   = tid + NT;
    const bool has1 = (e1 < ELEMS);
    const int row1 = e1 / HALO_W;
    const int col1 = e1 - row1 * HALO_W;
    const int gh1  = h0 + row1 - 1;
    const int gw1  = w0 + col1 - 1;
    const bool valid1 = has1 && ((unsigned)gh1 < (unsigned)Hn) && ((unsigned)gw1 < (unsigned)Wn);
    const bool intr1  = has1 && (row1 <= TILE_H) && (col1 >= 1) && (col1 <= TILE_W);  // row1>=16>=1 auto
    const long off1 = (long)gh1 * Wn + gw1;

    float connAcc = 0.0f;
    unsigned int bits0 = 0u, bits1 = 0u;

    // ---------------- Pass A: atts log-sigmoid tiles + con bits + conn BCE(atts)
    if (valid0) {
        const float* pa = atts + baseB + off0;
        const float* pc = con  + baseB + off0;
#pragma unroll 2
        for (int c = 0; c < Cn; c++) {
            const float x = __ldg(pa + (long)c * HWn);
            const float s = LN2 * lg2f(1.0f + ex2f(x * L2E));  // softplus(x)
            lpf[c * ELEMS + sidx0] = x - s;                    // log sigmoid(x)
            if (intr0) {
                const float t = __ldg(pc + (long)c * HWn);
                connAcc += s - t * x;
                bits0 |= (t > 0.5f) ? (1u << c) : 0u;
            }
        }
    } else {
#pragma unroll
        for (int c = 0; c < Cn; c++) lpf[c * ELEMS + sidx0] = -1e30f;
    }
    if (has1) {
        if (valid1) {
            const float* pa = atts + baseB + off1;
            const float* pc = con  + baseB + off1;
#pragma unroll 2
            for (int c = 0; c < Cn; c++) {
                const float x = __ldg(pa + (long)c * HWn);
                const float s = LN2 * lg2f(1.0f + ex2f(x * L2E));
                lpf[c * ELEMS + e1] = x - s;
                if (intr1) {
                    const float t = __ldg(pc + (long)c * HWn);
                    connAcc += s - t * x;
                    bits1 |= (t > 0.5f) ? (1u << c) : 0u;
                }
            }
        } else {
#pragma unroll
            for (int c = 0; c < Cn; c++) lpf[c * ELEMS + e1] = -1e30f;
        }
    }
    if (intr0) conb[row0 - 1][col0 - 1] = bits0;
    if (intr1) conb[row1 - 1][col1 - 1] = bits1;
    __syncthreads();

    // ---------------- Combine A (atts): bic1, sv1
    const unsigned int cb = conb[ty][tx];
    const int ci = (ty + 1) * HALO_W + (tx + 1);   // center index within a tile

    float bic1 = 0.0f, sv1 = 0.0f;
#pragma unroll
    for (int k = 0; k < 8; k++) {
        const float lv = lpf[k * ELEMS + ci]
                       + lpf[(7 - k) * ELEMS + ci + DH[k] * HALO_W + DW[k]];
        const float v = ex2f(lv * L2E);
        sv1 += v;
        bic1 -= ((cb >> k) & 1u) ? fmaxf(lv, -100.0f)
                                 : fmaxf(LN2 * lg2f(1.0f - v), -100.0f);
    }
    __syncthreads();   // done reading lpf before pass B overwrites it

    // ---------------- Pass B: dets (t from register bits; borders persist from A)
    if (valid0) {
        const float* pd = dets + baseB + off0;
#pragma unroll 2
        for (int c = 0; c < Cn; c++) {
            const float x = __ldg(pd + (long)c * HWn);
            const float s = LN2 * lg2f(1.0f + ex2f(x * L2E));
            lpf[c * ELEMS + sidx0] = x - s;
            if (intr0) {
                const float t = ((bits0 >> c) & 1u) ? 1.0f : 0.0f;
                connAcc += s - t * x;
            }
        }
    }
    if (valid1) {
        const float* pd = dets + baseB + off1;
#pragma unroll 2
        for (int c = 0; c < Cn; c++) {
            const float x = __ldg(pd + (long)c * HWn);
            const float s = LN2 * lg2f(1.0f + ex2f(x * L2E));
            lpf[c * ELEMS + e1] = x - s;
            if (intr1) {
                const float t = ((bits1 >> c) & 1u) ? 1.0f : 0.0f;
                connAcc += s - t * x;
            }
        }
    }
    __syncthreads();

    // ---------------- Combine B (dets): bic2, sv2, min
    float bic2 = 0.0f, sv2 = 0.0f, mv2 = 1e30f;
#pragma unroll
    for (int k = 0; k < 8; k++) {
        const float lv = lpf[k * ELEMS + ci]
                       + lpf[(7 - k) * ELEMS + ci + DH[k] * HALO_W + DW[k]];
        const float v = ex2f(lv * L2E);
        sv2 += v;
        mv2 = fminf(mv2, v);
        bic2 -= ((cb >> k) & 1u) ? fmaxf(lv, -100.0f)
                                 : fmaxf(LN2 * lg2f(1.0f - v), -100.0f);
    }

    // ---------------- Per-pixel tails
    const float tgt  = __ldg(target + (long)b * HWn + (long)(h0 + ty) * Wn + (w0 + tx));
    const bool  tpos = (tgt > 0.5f);

    const float g1   = sv1 * 0.125f;
    const float bce1 = tpos ? -fmaxf(LN2 * lg2f(g1),        -100.0f)
                            : -fmaxf(LN2 * lg2f(1.0f - g1), -100.0f);

    const int  cnt  = __popc(cb & 0xFFu);
    const bool edge = (cnt > 0) && (cnt < 8);
    const float g2  = sv2 * 0.125f;
    const float dec = edge ? (1.0f - mv2) : g2;
    const float de2 = tpos ? -fmaxf(LN2 * lg2f(dec),        -100.0f)
                           : -fmaxf(LN2 * lg2f(1.0f - dec), -100.0f);

    float cNC = 0.2f * (bic1 + bic2) + 0.8f * connAcc;   // / (B*C*H*W)
    float cNP = bce1 + de2;                              // / (B*H*W)

    // ---------------- Block reduction -> g_part[bid]
#pragma unroll
    for (int off = 16; off > 0; off >>= 1) {
        cNC += __shfl_xor_sync(0xFFFFFFFFu, cNC, off);
        cNP += __shfl_xor_sync(0xFFFFFFFFu, cNP, off);
    }
    const int lane = tid & 31;
    const int wid  = tid >> 5;
    if (lane == 0) { r0[wid] = cNC; r1[wid] = cNP; }
    __syncthreads();

    if (tid == 0) {
        float a = 0.0f, c2 = 0.0f;
#pragma unroll
        for (int i = 0; i < 16; i++) { a += r0[i]; c2 += r1[i]; }
        const int bid = blockIdx.x + GRID_X * (blockIdx.y + GRID_Y * blockIdx.z);
        g_part[bid] = make_float2(a, c2);
        __threadfence();
        const unsigned int ticket = atomicAdd(&g_ticket, 1u);
        s_last = (ticket == NBLOCKS - 1) ? 1 : 0;
    }
    __syncthreads();

    // ---------------- Last block: final deterministic reduction + output
    if (s_last) {
        __threadfence();
        double a = 0.0, c2 = 0.0;
        for (int i = tid; i < NBLOCKS; i += NT) {
            const float2 p = g_part[i];
            a  += (double)p.x;
            c2 += (double)p.y;
        }
#pragma unroll
        for (int off = 16; off > 0; off >>= 1) {
            a  += __shfl_xor_sync(0xFFFFFFFFu, a,  off);
            c2 += __shfl_xor_sync(0xFFFFFFFFu, c2, off);
        }
        __shared__ double d0[16], d1[16];
        if (lane == 0) { d0[wid] = a; d1[wid] = c2; }
        __syncthreads();
        if (wid == 0) {
            double x = (lane < 16) ? d0[lane] : 0.0;
            double y = (lane < 16) ? d1[lane] : 0.0;
#pragma unroll
            for (int off = 8; off > 0; off >>= 1) {
                x += __shfl_xor_sync(0xFFFFFFFFu, x, off);
                y += __shfl_xor_sync(0xFFFFFFFFu, y, off);
            }
            if (lane == 0) {
                const double invNC = 1.0 / (double)(Bn * Cn * Hn * Wn);
                const double invNP = 1.0 / (double)(Bn * Hn * Wn);
                out[0] = (float)(x * invNC + y * invNP);
                g_ticket = 0;   // reset for next graph replay
            }
        }
    }
}

extern "C" void kernel_launch(void* const* d_in, const int* in_sizes, int n_in,
                              void* d_out, int out_size)
{
    const float* atts   = (const float*)d_in[0];
    const float* dets   = (const float*)d_in[1];
    const float* target = (const float*)d_in[2];
    const float* con    = (const float*)d_in[3];
    float* out = (float*)d_out;

    cudaFuncSetAttribute(bicon_kernel,
                         cudaFuncAttributePreferredSharedMemoryCarveout, 50);

    dim3 grid(GRID_X, GRID_Y, Bn);
    bicon_kernel<<<grid, NT>>>(atts, dets, target, con, out);
}